// round 9
// baseline (speedup 1.0000x reference)
#include <cuda_runtime.h>

// SpikingAttentionJAX — ONE kernel, ZERO grid synchronization, minimal
// redundant work: 125 blocks x 1024 threads; each block owns a 1024-entry
// vocab slice and histograms the whole 8192-token stream (only 8 tokens per
// thread, L2-broadcast across blocks) into shared memory.
//
// LIF scan collapses to per-token occurrence counts (per-entry updates
// commute; entry t's final state depends only on count n_t and v0[t]).
// Then: replay n_t LIF steps, write gain (0.6 spiked / 1.0), REDUX warp
// top-5 -> warp0 block merge -> g_cand; done-counter: LAST arriving block
// merges 625 candidates and writes the 5 winners (1.5). JAX top_k tie-break
// (lower index wins) via REDUX.UMIN on index / packed (val<<32 | ~idx) keys.

static constexpr float DECAY     = 0.7f;
static constexpr float THETA     = 1.0f;
static constexpr float GAIN_UP   = 1.5f;
static constexpr float GAIN_DOWN = 0.6f;
static constexpr int   KW   = 5;
static constexpr int   NT   = 1024;
static constexpr int   NW   = NT / 32;       // 32 warps
static constexpr int   MAXB = 256;           // >= grid (125)

__device__ unsigned long long g_cand[MAXB * KW];
__device__ unsigned g_done = 0;              // monotonic across graph replays

__device__ __forceinline__ unsigned ordered_bits(float f) {
    unsigned u = __float_as_uint(f);
    return (u & 0x80000000u) ? ~u : (u | 0x80000000u);
}

__global__ __launch_bounds__(NT)
void k_main(const int* __restrict__ tok, const float* __restrict__ v0,
            float* __restrict__ out, int seq, int vocab, int nblocks) {
    const int tid  = threadIdx.x;
    const int lane = tid & 31;
    const int wid  = tid >> 5;
    const int base = blockIdx.x * NT;            // this block's vocab slice
    const int i    = base + tid;                 // this thread's vocab entry

    __shared__ int      sh_cnt[NT];
    __shared__ unsigned s_val[NW * KW];          // 160 block candidates
    __shared__ unsigned s_idx[NW * KW];
    __shared__ unsigned long long s_w[NW];
    __shared__ unsigned long long s_best;
    __shared__ unsigned s_last;

    sh_cnt[tid] = 0;
    __syncthreads();

    // ---- histogram the whole token stream for this vocab slice ----
    // seq=8192 -> 2048 int4 -> 2 int4 per thread. Hits are rare (~64/block).
    const int4* tok4 = reinterpret_cast<const int4*>(tok);
    const int   n4   = seq >> 2;
    for (int c = tid; c < n4; c += NT) {
        int4 t4 = __ldg(&tok4[c]);
        int t;
        t = t4.x; t = t < 0 ? 0 : (t >= vocab ? vocab - 1 : t);
        if ((unsigned)(t - base) < (unsigned)NT) atomicAdd(&sh_cnt[t - base], 1);
        t = t4.y; t = t < 0 ? 0 : (t >= vocab ? vocab - 1 : t);
        if ((unsigned)(t - base) < (unsigned)NT) atomicAdd(&sh_cnt[t - base], 1);
        t = t4.z; t = t < 0 ? 0 : (t >= vocab ? vocab - 1 : t);
        if ((unsigned)(t - base) < (unsigned)NT) atomicAdd(&sh_cnt[t - base], 1);
        t = t4.w; t = t < 0 ? 0 : (t >= vocab ? vocab - 1 : t);
        if ((unsigned)(t - base) < (unsigned)NT) atomicAdd(&sh_cnt[t - base], 1);
    }
    for (int c = (n4 << 2) + tid; c < seq; c += NT) {   // tail if seq % 4 != 0
        int t = __ldg(&tok[c]);
        t = t < 0 ? 0 : (t >= vocab ? vocab - 1 : t);
        if ((unsigned)(t - base) < (unsigned)NT) atomicAdd(&sh_cnt[t - base], 1);
    }
    __syncthreads();

    // ---- LIF replay + gains ----
    unsigned uval = 0u;                          // 0 = invalid/popped sentinel
    unsigned idx  = (unsigned)i;
    if (i < vocab) {
        int   cnt = sh_cnt[tid];
        float v   = __ldg(&v0[i]);
        int s = 0;
        for (int it = 0; it < cnt; it++) {
            float vn = DECAY * v + 1.0f;
            if (vn >= THETA) { v = vn - THETA; s++; }
            else             { v = vn; }
        }
        out[i] = (s > 0) ? GAIN_DOWN : 1.0f;
        uval = ordered_bits(v);
    }

    // ---- warp top-5: REDUX.UMAX(value) + REDUX.UMIN(index) per round ----
    #pragma unroll
    for (int r = 0; r < KW; r++) {
        unsigned m    = __reduce_max_sync(0xffffffffu, uval);
        unsigned cand = (uval == m) ? idx : 0xffffffffu;
        unsigned wi   = __reduce_min_sync(0xffffffffu, cand);
        if (lane == 0) { s_val[wid * KW + r] = m; s_idx[wid * KW + r] = wi; }
        if (uval == m && idx == wi) uval = 0u;
    }
    __syncthreads();

    // ---- warp 0: merge 160 (val,idx) -> block top-5 -> g_cand ----
    if (wid == 0) {
        unsigned av[KW], ai[KW];                 // 5 slots per lane, static idx
        #pragma unroll
        for (int s = 0; s < KW; s++) {
            av[s] = s_val[s * 32 + lane];
            ai[s] = s_idx[s * 32 + lane];
        }
        #pragma unroll
        for (int r = 0; r < KW; r++) {
            unsigned bv = av[0], bi = ai[0];
            #pragma unroll
            for (int s = 1; s < KW; s++) {
                bool better = (av[s] > bv) || (av[s] == bv && ai[s] < bi);
                if (better) { bv = av[s]; bi = ai[s]; }
            }
            unsigned m    = __reduce_max_sync(0xffffffffu, bv);
            unsigned cand = (bv == m) ? bi : 0xffffffffu;
            unsigned wi   = __reduce_min_sync(0xffffffffu, cand);
            if (lane == 0)
                g_cand[blockIdx.x * KW + r] =
                    ((unsigned long long)m << 32) |
                    (unsigned long long)(0xffffffffu - wi);
            #pragma unroll
            for (int s = 0; s < KW; s++)
                if (av[s] == m && ai[s] == wi) { av[s] = 0u; ai[s] = 0xffffffffu; }
        }
    }

    // ---- done-counter: last-arriving block merges (no spinning) ----
    if (tid == 0) {
        __threadfence();                         // publish g_cand
        unsigned old = atomicAdd(&g_done, 1);
        s_last = (((old + 1) % (unsigned)nblocks) == 0u) ? 1u : 0u;
    }
    __syncthreads();
    if (!s_last) return;
    __threadfence();                             // acquire g_cand writes

    const int ncand = nblocks * KW;              // 625 <= 1024 threads
    unsigned long long key = (tid < ncand) ? g_cand[tid] : 0ull;

    #pragma unroll
    for (int r = 0; r < KW; r++) {
        unsigned hv = (unsigned)(key >> 32);
        unsigned wm = __reduce_max_sync(0xffffffffu, hv);
        unsigned lo = (hv == wm) ? (unsigned)(key & 0xffffffffull) : 0u;
        unsigned wl = __reduce_max_sync(0xffffffffu, lo);  // max ~idx = min idx
        if (lane == 0) s_w[wid] = ((unsigned long long)wm << 32) | wl;
        __syncthreads();
        if (wid == 0) {
            unsigned long long a = s_w[lane];    // NW == 32 exactly
            unsigned ahv = (unsigned)(a >> 32);
            unsigned awm = __reduce_max_sync(0xffffffffu, ahv);
            unsigned alo = (ahv == awm) ? (unsigned)(a & 0xffffffffull) : 0u;
            unsigned awl = __reduce_max_sync(0xffffffffu, alo);
            if (lane == 0) {
                unsigned long long b = ((unsigned long long)awm << 32) | awl;
                s_best = b;
                unsigned oidx = 0xffffffffu - awl;
                out[oidx] = GAIN_UP;             // >=5 unique real keys exist
            }
        }
        __syncthreads();
        if (key == s_best) key = 0ull;           // pop winner (keys unique)
        __syncthreads();
    }
}

// ---------------------------------------------------------------- launch
extern "C" void kernel_launch(void* const* d_in, const int* in_sizes, int n_in,
                              void* d_out, int out_size) {
    const int*   tok = (const int*)d_in[0];
    const float* v0  = (const float*)d_in[1];
    const int seq   = in_sizes[0];
    const int vocab = in_sizes[1];
    float* out = (float*)d_out;

    int gblocks = (vocab + NT - 1) / NT;         // 125 for vocab=128000
    if (gblocks > MAXB) gblocks = MAXB;          // never hit at this size
    k_main<<<gblocks, NT>>>(tok, v0, out, seq, vocab, gblocks);
}

// round 10
// speedup vs baseline: 1.0060x; 1.0060x over previous
#include <cuda_runtime.h>

// SpikingAttentionJAX — ONE kernel, ZERO grid sync, critical-path-minimized.
// LIF scan collapses to per-token occurrence counts (per-entry updates
// commute; entry t's final state depends only on count n_t and v0[t]).
//
// 125 blocks x 1024 threads; block b owns vocab slice [1024b, 1024b+1024).
// Each block histograms the whole 8192-token stream (8 tokens/thread, two
// independent int4 loads, L2-broadcast across blocks) into shared memory.
// v0 is prefetched BEFORE the histogram to overlap its DRAM latency.
// Then: LIF replay, gain store (0.6 spiked / 1.0), REDUX warp top-5,
// warp0 block merge -> g_cand; done-counter: LAST arriving block merges 625
// candidates (per-warp REDUX top-5, ONE barrier, warp0 register merge) and
// writes the 5 winners (1.5). JAX top_k tie-break (lower index wins) via
// REDUX.UMIN on index / packed monotone key (val<<32 | ~idx).

static constexpr float DECAY     = 0.7f;
static constexpr float THETA     = 1.0f;
static constexpr float GAIN_UP   = 1.5f;
static constexpr float GAIN_DOWN = 0.6f;
static constexpr int   KW   = 5;
static constexpr int   NT   = 1024;
static constexpr int   NW   = NT / 32;       // 32 warps
static constexpr int   MAXB = 256;           // >= grid (125)

__device__ unsigned long long g_cand[MAXB * KW];
__device__ unsigned g_done = 0;              // monotonic across graph replays

__device__ __forceinline__ unsigned ordered_bits(float f) {
    unsigned u = __float_as_uint(f);
    return (u & 0x80000000u) ? ~u : (u | 0x80000000u);
}

__global__ __launch_bounds__(NT)
void k_main(const int* __restrict__ tok, const float* __restrict__ v0,
            float* __restrict__ out, int seq, int vocab, int nblocks) {
    const int tid  = threadIdx.x;
    const int lane = tid & 31;
    const int wid  = tid >> 5;
    const int base = blockIdx.x * NT;            // this block's vocab slice
    const int i    = base + tid;                 // this thread's vocab entry
    const bool live = (i < vocab);

    __shared__ int                sh_cnt[NT];
    __shared__ unsigned           s_val[NW * KW];   // 160 block candidates
    __shared__ unsigned           s_idx[NW * KW];
    __shared__ unsigned long long s_m[NW * KW];     // finalizer candidates
    __shared__ unsigned           s_last;

    // ---- prefetch v0 early: independent of histogram, hides DRAM latency ----
    float vpre = live ? __ldg(&v0[i]) : 0.0f;

    sh_cnt[tid] = 0;
    __syncthreads();

    // ---- histogram whole token stream for this slice (2 indep int4/thread) ----
    const int4* tok4 = reinterpret_cast<const int4*>(tok);
    const int   n4   = seq >> 2;                 // 2048
    int4 ta, tb;
    bool hasA = (tid < n4), hasB = (tid + NT < n4);
    if (hasA) ta = __ldg(&tok4[tid]);
    if (hasB) tb = __ldg(&tok4[tid + NT]);
    if (hasA) {
        int t;
        t = ta.x; t = t < 0 ? 0 : (t >= vocab ? vocab - 1 : t);
        if ((unsigned)(t - base) < (unsigned)NT) atomicAdd(&sh_cnt[t - base], 1);
        t = ta.y; t = t < 0 ? 0 : (t >= vocab ? vocab - 1 : t);
        if ((unsigned)(t - base) < (unsigned)NT) atomicAdd(&sh_cnt[t - base], 1);
        t = ta.z; t = t < 0 ? 0 : (t >= vocab ? vocab - 1 : t);
        if ((unsigned)(t - base) < (unsigned)NT) atomicAdd(&sh_cnt[t - base], 1);
        t = ta.w; t = t < 0 ? 0 : (t >= vocab ? vocab - 1 : t);
        if ((unsigned)(t - base) < (unsigned)NT) atomicAdd(&sh_cnt[t - base], 1);
    }
    if (hasB) {
        int t;
        t = tb.x; t = t < 0 ? 0 : (t >= vocab ? vocab - 1 : t);
        if ((unsigned)(t - base) < (unsigned)NT) atomicAdd(&sh_cnt[t - base], 1);
        t = tb.y; t = t < 0 ? 0 : (t >= vocab ? vocab - 1 : t);
        if ((unsigned)(t - base) < (unsigned)NT) atomicAdd(&sh_cnt[t - base], 1);
        t = tb.z; t = t < 0 ? 0 : (t >= vocab ? vocab - 1 : t);
        if ((unsigned)(t - base) < (unsigned)NT) atomicAdd(&sh_cnt[t - base], 1);
        t = tb.w; t = t < 0 ? 0 : (t >= vocab ? vocab - 1 : t);
        if ((unsigned)(t - base) < (unsigned)NT) atomicAdd(&sh_cnt[t - base], 1);
    }
    // scalar tail only if seq % 4 != 0 or seq > 8*NT (not the case here)
    for (int c = (n4 > 2 * NT ? 2 * NT : n4) + tid; c < n4; c += NT) {
        int4 t4 = __ldg(&tok4[c]);
        int t;
        t = t4.x; t = t < 0 ? 0 : (t >= vocab ? vocab - 1 : t);
        if ((unsigned)(t - base) < (unsigned)NT) atomicAdd(&sh_cnt[t - base], 1);
        t = t4.y; t = t < 0 ? 0 : (t >= vocab ? vocab - 1 : t);
        if ((unsigned)(t - base) < (unsigned)NT) atomicAdd(&sh_cnt[t - base], 1);
        t = t4.z; t = t < 0 ? 0 : (t >= vocab ? vocab - 1 : t);
        if ((unsigned)(t - base) < (unsigned)NT) atomicAdd(&sh_cnt[t - base], 1);
        t = t4.w; t = t < 0 ? 0 : (t >= vocab ? vocab - 1 : t);
        if ((unsigned)(t - base) < (unsigned)NT) atomicAdd(&sh_cnt[t - base], 1);
    }
    for (int c = (n4 << 2) + tid; c < seq; c += NT) {
        int t = __ldg(&tok[c]);
        t = t < 0 ? 0 : (t >= vocab ? vocab - 1 : t);
        if ((unsigned)(t - base) < (unsigned)NT) atomicAdd(&sh_cnt[t - base], 1);
    }
    __syncthreads();

    // ---- LIF replay + gains ----
    unsigned uval = 0u;                          // 0 = invalid/popped sentinel
    unsigned idx  = (unsigned)i;
    if (live) {
        int   cnt = sh_cnt[tid];
        float v   = vpre;
        int s = 0;
        for (int it = 0; it < cnt; it++) {
            float vn = DECAY * v + 1.0f;
            if (vn >= THETA) { v = vn - THETA; s++; }
            else             { v = vn; }
        }
        out[i] = (s > 0) ? GAIN_DOWN : 1.0f;
        uval = ordered_bits(v);
    }

    // ---- warp top-5: REDUX.UMAX(value) + REDUX.UMIN(index) per round ----
    #pragma unroll
    for (int r = 0; r < KW; r++) {
        unsigned m    = __reduce_max_sync(0xffffffffu, uval);
        unsigned cand = (uval == m) ? idx : 0xffffffffu;
        unsigned wi   = __reduce_min_sync(0xffffffffu, cand);
        if (lane == 0) { s_val[wid * KW + r] = m; s_idx[wid * KW + r] = wi; }
        if (uval == m && idx == wi) uval = 0u;
    }
    __syncthreads();

    // ---- warp 0: merge 160 (val,idx) -> block top-5 -> g_cand ----
    if (wid == 0) {
        unsigned av[KW], ai[KW];                 // 5 slots per lane, static idx
        #pragma unroll
        for (int s = 0; s < KW; s++) {
            av[s] = s_val[s * 32 + lane];
            ai[s] = s_idx[s * 32 + lane];
        }
        #pragma unroll
        for (int r = 0; r < KW; r++) {
            unsigned bv = av[0], bi = ai[0];
            #pragma unroll
            for (int s = 1; s < KW; s++) {
                bool better = (av[s] > bv) || (av[s] == bv && ai[s] < bi);
                if (better) { bv = av[s]; bi = ai[s]; }
            }
            unsigned m    = __reduce_max_sync(0xffffffffu, bv);
            unsigned cand = (bv == m) ? bi : 0xffffffffu;
            unsigned wi   = __reduce_min_sync(0xffffffffu, cand);
            if (lane == 0)
                g_cand[blockIdx.x * KW + r] =
                    ((unsigned long long)m << 32) |
                    (unsigned long long)(0xffffffffu - wi);
            #pragma unroll
            for (int s = 0; s < KW; s++)
                if (av[s] == m && ai[s] == wi) { av[s] = 0u; ai[s] = 0xffffffffu; }
        }
    }

    // ---- done-counter: last-arriving block finalizes (no spinning) ----
    if (tid == 0) {
        __threadfence();                         // publish g_cand (release)
        unsigned old = atomicAdd(&g_done, 1);
        s_last = (((old + 1) % (unsigned)nblocks) == 0u) ? 1u : 0u;
    }
    __syncthreads();
    if (!s_last) return;
    __threadfence();                             // acquire g_cand writes

    // ---- finalizer: 625 keys -> per-warp top-5 (sync-free) -> 1 BAR -> warp0 ----
    const int ncand = nblocks * KW;              // 625 <= 1024
    unsigned long long key = (tid < ncand) ? g_cand[tid] : 0ull;
    unsigned hv = (unsigned)(key >> 32);
    unsigned lo = (unsigned)(key & 0xffffffffull);

    #pragma unroll
    for (int r = 0; r < KW; r++) {
        unsigned wm = __reduce_max_sync(0xffffffffu, hv);
        unsigned cl = (hv == wm) ? lo : 0u;
        unsigned wl = __reduce_max_sync(0xffffffffu, cl);  // max ~idx = min idx
        if (lane == 0) s_m[wid * KW + r] = ((unsigned long long)wm << 32) | wl;
        if (hv == wm && lo == wl) { hv = 0u; lo = 0u; }    // pop (keys unique)
    }
    __syncthreads();                             // single barrier in finalize

    if (wid == 0) {
        unsigned long long a[KW];                // 5 slots/lane over 160 keys
        #pragma unroll
        for (int s = 0; s < KW; s++) a[s] = s_m[s * 32 + lane];
        #pragma unroll
        for (int r = 0; r < KW; r++) {
            unsigned long long b = a[0];
            #pragma unroll
            for (int s = 1; s < KW; s++) if (a[s] > b) b = a[s];  // packed key: monotone
            unsigned bh = (unsigned)(b >> 32);
            unsigned wm = __reduce_max_sync(0xffffffffu, bh);
            unsigned bl = (bh == wm) ? (unsigned)(b & 0xffffffffull) : 0u;
            unsigned wl = __reduce_max_sync(0xffffffffu, bl);
            if (lane == 0 && wm != 0u) {
                unsigned oidx = 0xffffffffu - wl;
                out[oidx] = GAIN_UP;             // >=5 unique real keys exist
            }
            unsigned long long win = ((unsigned long long)wm << 32) | wl;
            #pragma unroll
            for (int s = 0; s < KW; s++) if (a[s] == win) a[s] = 0ull;
        }
    }
}

// ---------------------------------------------------------------- launch
extern "C" void kernel_launch(void* const* d_in, const int* in_sizes, int n_in,
                              void* d_out, int out_size) {
    const int*   tok = (const int*)d_in[0];
    const float* v0  = (const float*)d_in[1];
    const int seq   = in_sizes[0];
    const int vocab = in_sizes[1];
    float* out = (float*)d_out;

    int gblocks = (vocab + NT - 1) / NT;         // 125 for vocab=128000
    if (gblocks > MAXB) gblocks = MAXB;          // never hit at this size
    k_main<<<gblocks, NT>>>(tok, v0, out, seq, vocab, gblocks);
}